// round 10
// baseline (speedup 1.0000x reference)
#include <cuda_runtime.h>
#include <cuda_fp16.h>
#include <cstdint>

// ---------------------------------------------------------------------------
// EdgeConv (mlp_layer=0, aggregate=max), restructured:
//   t      = feat @ theta_w                      [N, 64]
//   base   = t + feat @ phi_w + theta_b + phi_b  [N, 64]   (fp16 scratch)
//   out[v] = base[v] - min_k t[nbr[v,k]]         (per-feature min, fp32 out)
//
// GEMM: mma.sync m16n8k16 fp16, 2-pass A split (t ~= (Ahi+Alo)*Bhi).
// B staged in-kernel as fp16 [k][c] (coalesced, conflict-free) and fragments
// loaded via ldmatrix.x4.trans -> no separate prep kernel.
// Gather: fp16 t + fp16 base, 2 nodes/warp, writes fp32 out directly.
// ---------------------------------------------------------------------------

#define F_DIM 64
#define N_MAX 120000

__device__ __half g_t16[(size_t)N_MAX * F_DIM];     // fp16 t
__device__ __half g_base16[(size_t)N_MAX * F_DIM];  // fp16 base

// ============================= PTX helpers =================================
__device__ __forceinline__ uint32_t smem_u32(const void* p) {
    uint32_t a;
    asm("{ .reg .u64 tmp; cvta.to.shared.u64 tmp, %1; cvt.u32.u64 %0, tmp; }"
        : "=r"(a) : "l"(p));
    return a;
}

__device__ __forceinline__ void ldsm_x4(uint32_t* r, uint32_t addr) {
    asm volatile("ldmatrix.sync.aligned.m8n8.x4.shared.b16 {%0,%1,%2,%3}, [%4];"
                 : "=r"(r[0]), "=r"(r[1]), "=r"(r[2]), "=r"(r[3]) : "r"(addr));
}

__device__ __forceinline__ void ldsm_x4_trans(uint32_t* r, uint32_t addr) {
    asm volatile("ldmatrix.sync.aligned.m8n8.x4.trans.shared.b16 {%0,%1,%2,%3}, [%4];"
                 : "=r"(r[0]), "=r"(r[1]), "=r"(r[2]), "=r"(r[3]) : "r"(addr));
}

__device__ __forceinline__ void mma16816(float* c, const uint32_t* a,
                                         const uint32_t* b) {
    asm volatile(
        "mma.sync.aligned.m16n8k16.row.col.f32.f16.f16.f32 "
        "{%0,%1,%2,%3}, {%4,%5,%6,%7}, {%8,%9}, {%0,%1,%2,%3};"
        : "+f"(c[0]), "+f"(c[1]), "+f"(c[2]), "+f"(c[3])
        : "r"(a[0]), "r"(a[1]), "r"(a[2]), "r"(a[3]), "r"(b[0]), "r"(b[1]));
}

// fp16 hi/lo split of two floats -> packed hi word + lo word
__device__ __forceinline__ uint32_t pack_hilo(float x, float y,
                                              uint32_t& lo_out) {
    __half hx = __float2half_rn(x);
    __half hy = __float2half_rn(y);
    __half lx = __float2half_rn(x - __half2float(hx));
    __half ly = __float2half_rn(y - __half2float(hy));
    lo_out = (uint32_t)__half_as_ushort(lx) |
             ((uint32_t)__half_as_ushort(ly) << 16);
    return (uint32_t)__half_as_ushort(hx) |
           ((uint32_t)__half_as_ushort(hy) << 16);
}

// SMEM layout (dynamic, bytes):
//   sAH/sAL: 64 rows x 72 fp16 (144 B rows; ldmatrix conflict-free)
//   sB16:    64 k-rows x 136 fp16 (272 B rows; c<64 theta, c>=64 phi;
//            272 B stride -> 8 consecutive k-rows hit distinct bank groups)
#define SM_AH  0
#define SM_AL  9216
#define SM_B16 18432
#define SM_BYTES (18432 + 64 * 272)    // 35840

// ============================ GEMM kernel ==================================
// CTA: 64 rows x full N=128 ([theta|phi]). 8 warps: wm=(wid&1)*32,
// wn=(wid>>1)*16. Warp owns theta cols wn..wn+15 and phi cols 64+wn..64+wn+15
// -> t and base combine in registers.
__global__ __launch_bounds__(256, 4)
void gemm_mma_kernel(const float* __restrict__ feat,
                     const float* __restrict__ theta_w,
                     const float* __restrict__ theta_b,
                     const float* __restrict__ phi_w,
                     const float* __restrict__ phi_b,
                     int n)
{
    extern __shared__ char sm[];
    const uint32_t sbase = smem_u32(sm);
    const int tid = threadIdx.x;
    const int rb  = blockIdx.x * 64;

    // ---- stage A: feat[rb..rb+63][0..63] -> fp16 hi/lo (coalesced f4) -----
#pragma unroll
    for (int p = 0; p < 4; p++) {
        int idx = tid + p * 256;         // 0..1023
        int c4  = idx & 15;              // float4 column group
        int row = idx >> 4;              // 0..63
        float4 f = make_float4(0.f, 0.f, 0.f, 0.f);
        int gr = rb + row;
        if (gr < n) f = *(const float4*)&feat[(size_t)gr * F_DIM + c4 * 4];
        uint32_t l0, l1;
        uint32_t h0 = pack_hilo(f.x, f.y, l0);
        uint32_t h1 = pack_hilo(f.z, f.w, l1);
        uint32_t off = row * 144 + c4 * 8;
        *(uint2*)(sm + SM_AH + off) = make_uint2(h0, h1);
        *(uint2*)(sm + SM_AL + off) = make_uint2(l0, l1);
    }

    // ---- stage B fp16 [k][c] (coalesced loads, conflict-free stores) ------
#pragma unroll
    for (int p = 0; p < 8; p++) {
        int idx = tid + p * 256;         // 0..2047 float4 groups
        int k   = idx >> 5;              // 0..63
        int c4  = idx & 31;              // combined-c float4 group
        int hsel = c4 >> 4;              // 0 theta, 1 phi
        int cc   = (c4 & 15) * 4;
        const float* w = hsel ? phi_w : theta_w;
        float4 v = *(const float4*)&w[k * F_DIM + cc];
        __half2 h01 = __floats2half2_rn(v.x, v.y);
        __half2 h23 = __floats2half2_rn(v.z, v.w);
        *(uint2*)(sm + SM_B16 + k * 272 + (hsel * 64 + cc) * 2) =
            make_uint2(*(uint32_t*)&h01, *(uint32_t*)&h23);
    }
    __syncthreads();

    const int wid  = tid >> 5;
    const int lane = tid & 31;
    const int wm   = (wid & 1) * 32;
    const int wn   = (wid >> 1) * 16;
    const int li   = lane & 7;
    const int lg   = lane >> 3;

    float accT[2][2][4], accP[2][2][4];
#pragma unroll
    for (int mt = 0; mt < 2; mt++)
#pragma unroll
        for (int nt = 0; nt < 2; nt++)
#pragma unroll
            for (int j = 0; j < 4; j++) {
                accT[mt][nt][j] = 0.f;
                accP[mt][nt][j] = 0.f;
            }

#pragma unroll
    for (int ks = 0; ks < 4; ks++) {
        const int k0 = ks * 16;
        // ---- B fragments via ldmatrix.trans on [k][c] --------------------
        // lane groups: g0 -> (k0..k0+7,  n0)   = b0 tile0
        //              g1 -> (k0+8..15,  n0)   = b1 tile0
        //              g2 -> (k0..k0+7,  n0+8) = b0 tile1
        //              g3 -> (k0+8..15,  n0+8) = b1 tile1
        uint32_t bT[2][2], bP[2][2];
        {
            int kr = k0 + li + (lg & 1) * 8;
            int nc = wn + (lg >> 1) * 8;
            uint32_t base = sbase + SM_B16 + kr * 272 + nc * 2;
            uint32_t r[4];
            ldsm_x4_trans(r, base);            // theta cols
            bT[0][0] = r[0]; bT[0][1] = r[1];
            bT[1][0] = r[2]; bT[1][1] = r[3];
            ldsm_x4_trans(r, base + 128);      // phi cols (+64 halfs)
            bP[0][0] = r[0]; bP[0][1] = r[1];
            bP[1][0] = r[2]; bP[1][1] = r[3];
        }
        // ---- two A passes (hi, lo) share the B fragments -------------------
#pragma unroll
        for (int p = 0; p < 2; p++) {
            const uint32_t aoff = p ? SM_AL : SM_AH;
            uint32_t a[2][4];
#pragma unroll
            for (int mt = 0; mt < 2; mt++) {
                int row = wm + mt * 16 + li + (lg & 1) * 8;
                int col = k0 + (lg >> 1) * 8;
                ldsm_x4(a[mt], sbase + aoff + row * 144 + col * 2);
            }
#pragma unroll
            for (int mt = 0; mt < 2; mt++)
#pragma unroll
                for (int nt = 0; nt < 2; nt++) {
                    mma16816(accT[mt][nt], a[mt], bT[nt]);
                    mma16816(accP[mt][nt], a[mt], bP[nt]);
                }
        }
    }

    // ---- epilogue: t (fp16) and base (fp16) --------------------------------
#pragma unroll
    for (int mt = 0; mt < 2; mt++) {
        int r0 = rb + wm + mt * 16 + (lane >> 2);
#pragma unroll
        for (int nt = 0; nt < 2; nt++) {
            int col = wn + nt * 8 + 2 * (lane & 3);
            float b0 = theta_b[col]     + phi_b[col];
            float b1 = theta_b[col + 1] + phi_b[col + 1];
            if (r0 < n) {
                size_t o = (size_t)r0 * F_DIM + col;
                float t0 = accT[mt][nt][0], t1 = accT[mt][nt][1];
                *(__half2*)&g_t16[o] = __floats2half2_rn(t0, t1);
                *(__half2*)&g_base16[o] =
                    __floats2half2_rn(t0 + accP[mt][nt][0] + b0,
                                      t1 + accP[mt][nt][1] + b1);
            }
            int r1 = r0 + 8;
            if (r1 < n) {
                size_t o = (size_t)r1 * F_DIM + col;
                float t2 = accT[mt][nt][2], t3 = accT[mt][nt][3];
                *(__half2*)&g_t16[o] = __floats2half2_rn(t2, t3);
                *(__half2*)&g_base16[o] =
                    __floats2half2_rn(t2 + accP[mt][nt][2] + b0,
                                      t3 + accP[mt][nt][3] + b1);
            }
        }
    }
}

// ---------------------------------------------------------------------------
// Kernel 2: gather-min over fp16 t. TWO nodes per warp: lanes 0-15 -> node
// 2w, lanes 16-31 -> node 2w+1. Lane hl (0..15) owns uint2 chunk hl of the
// 128-B row (features 4hl..4hl+3). Indices: one coalesced load per lane,
// broadcast via shfl(width=16). Writes fp32 out = base16 - min (sole writer
// of out -> full coverage of the poisoned buffer).
// ---------------------------------------------------------------------------
__global__ __launch_bounds__(256)
void gather_min_kernel(const void* __restrict__ nbr_raw,
                       float* __restrict__ out,
                       int n, int K)
{
    const int lane = threadIdx.x & 31;

    // dtype detect (uniform): int64 indices < 2^31 have zero odd words
    unsigned int probe = ((const unsigned int*)nbr_raw)[lane];
    bool oddzero = ((lane & 1) == 0) || (probe == 0u);
    const bool is64 = (__ballot_sync(0xFFFFFFFFu, oddzero) == 0xFFFFFFFFu);

    long long wpair = (blockIdx.x * (long long)blockDim.x + threadIdx.x) >> 5;
    const int half = lane >> 4;      // 0 or 1
    const int hl   = lane & 15;      // chunk within row
    int node = (int)(wpair * 2) + half;
    if ((int)(wpair * 2) >= n) return;
    if (node >= n) node = n - 1;     // duplicate work on odd tail (benign)

    // my neighbor index (lane hl holds neighbor hl of my node)
    int myidx;
    if (K == 16) {
        myidx = is64 ? (int)((const long long*)nbr_raw)[(size_t)node * 16 + hl]
                     : ((const int*)nbr_raw)[(size_t)node * 16 + hl];
    } else {
        myidx = 0;
    }

    const uint2* tp = (const uint2*)g_t16;   // 16 uint2 per row
    __half2 m0 = __float2half2_rn(65504.f);
    __half2 m1 = m0;

    if (K == 16) {
#pragma unroll
        for (int j = 0; j < 16; j++) {
            int uj = __shfl_sync(0xFFFFFFFFu, myidx, j, 16);
            uint2 v = __ldg(&tp[uj * 16 + hl]);
            m0 = __hmin2(m0, *(__half2*)&v.x);
            m1 = __hmin2(m1, *(__half2*)&v.y);
        }
    } else {
        for (int j = 0; j < K; j++) {
            int uj = is64 ? (int)((const long long*)nbr_raw)[(size_t)node * K + j]
                          : ((const int*)nbr_raw)[(size_t)node * K + j];
            uint2 v = __ldg(&tp[uj * 16 + hl]);
            m0 = __hmin2(m0, *(__half2*)&v.x);
            m1 = __hmin2(m1, *(__half2*)&v.y);
        }
    }

    // base (fp16) -> out (fp32)
    size_t o = (size_t)node * 16 + hl;
    uint2 bb = *((const uint2*)g_base16 + o);
    float2 B0 = __half22float2(*(__half2*)&bb.x);
    float2 B1 = __half22float2(*(__half2*)&bb.y);
    float2 f0 = __half22float2(m0);
    float2 f1 = __half22float2(m1);
    float4* out4 = (float4*)out;
    out4[o] = make_float4(B0.x - f0.x, B0.y - f0.y,
                          B1.x - f1.x, B1.y - f1.y);
}

// ============================== launch =====================================
extern "C" void kernel_launch(void* const* d_in, const int* in_sizes, int n_in,
                              void* d_out, int out_size)
{
    const float* feat    = (const float*)d_in[0];
    const void*  nbr     = d_in[1];
    const float* theta_w = (const float*)d_in[2];
    const float* theta_b = (const float*)d_in[3];
    const float* phi_w   = (const float*)d_in[4];
    const float* phi_b   = (const float*)d_in[5];
    float* out = (float*)d_out;

    const int n = in_sizes[0] / F_DIM;     // number of nodes
    const int K = in_sizes[1] / n;         // neighbors per node (=16)

    int g1 = (n + 63) / 64;
    gemm_mma_kernel<<<g1, 256, SM_BYTES>>>(feat, theta_w, theta_b, phi_w,
                                           phi_b, n);

    long long pairs = ((long long)n + 1) / 2;        // 2 nodes per warp
    long long total_threads = pairs * 32;
    int g2 = (int)((total_threads + 255) / 256);
    gather_min_kernel<<<g2, 256>>>(nbr, out, n, K);
}

// round 11
// speedup vs baseline: 1.0007x; 1.0007x over previous
#include <cuda_runtime.h>
#include <cuda_fp16.h>
#include <cstdint>

// ---------------------------------------------------------------------------
// EdgeConv (mlp_layer=0, aggregate=max), restructured:
//   t      = feat @ theta_w                      [N, 64]
//   base   = t + feat @ phi_w + theta_b + phi_b  [N, 64]   (fp16 scratch)
//   out[v] = base[v] - min_k t[nbr[v,k]]         (per-feature min, fp32 out)
//
// GEMM: mma.sync m16n8k16 fp16, 2-pass A split (t ~= (Ahi+Alo)*Bhi).
// B pre-converted ONCE to fp16 [n][k] by a prep kernel -> GEMM stages it
// with coalesced uint4 copies and non-trans ldmatrix (proven fast path).
// Gather: fp16 t + fp16 base, 2 nodes/warp, writes fp32 out directly.
// ---------------------------------------------------------------------------

#define F_DIM 64
#define N_MAX 120000

__device__ __half g_t16[(size_t)N_MAX * F_DIM];     // fp16 t
__device__ __half g_base16[(size_t)N_MAX * F_DIM];  // fp16 base
__device__ __half g_Bh[128 * 64];                   // fp16 [nrow][k]; nrow<64
                                                    // theta col, >=64 phi col

// ============================= PTX helpers =================================
__device__ __forceinline__ uint32_t smem_u32(const void* p) {
    uint32_t a;
    asm("{ .reg .u64 tmp; cvta.to.shared.u64 tmp, %1; cvt.u32.u64 %0, tmp; }"
        : "=r"(a) : "l"(p));
    return a;
}

__device__ __forceinline__ void ldsm_x4(uint32_t* r, uint32_t addr) {
    asm volatile("ldmatrix.sync.aligned.m8n8.x4.shared.b16 {%0,%1,%2,%3}, [%4];"
                 : "=r"(r[0]), "=r"(r[1]), "=r"(r[2]), "=r"(r[3]) : "r"(addr));
}

__device__ __forceinline__ void mma16816(float* c, const uint32_t* a,
                                         const uint32_t* b) {
    asm volatile(
        "mma.sync.aligned.m16n8k16.row.col.f32.f16.f16.f32 "
        "{%0,%1,%2,%3}, {%4,%5,%6,%7}, {%8,%9}, {%0,%1,%2,%3};"
        : "+f"(c[0]), "+f"(c[1]), "+f"(c[2]), "+f"(c[3])
        : "r"(a[0]), "r"(a[1]), "r"(a[2]), "r"(a[3]), "r"(b[0]), "r"(b[1]));
}

// fp16 hi/lo split of two floats -> packed hi word + lo word
__device__ __forceinline__ uint32_t pack_hilo(float x, float y,
                                              uint32_t& lo_out) {
    __half hx = __float2half_rn(x);
    __half hy = __float2half_rn(y);
    __half lx = __float2half_rn(x - __half2float(hx));
    __half ly = __float2half_rn(y - __half2float(hy));
    lo_out = (uint32_t)__half_as_ushort(lx) |
             ((uint32_t)__half_as_ushort(ly) << 16);
    return (uint32_t)__half_as_ushort(hx) |
           ((uint32_t)__half_as_ushort(hy) << 16);
}

// SMEM layout (dynamic, bytes). Rows padded to 72 fp16 = 144 B (ldmatrix
// conflict-free: 8 rows x 144 B hit 8 distinct 16B bank groups).
#define SM_AH 0
#define SM_AL 9216
#define SM_BH 18432
#define SM_BYTES 36864

// ============================ prep kernel ==================================
// One-off: g_Bh[nrow][k] = fp16(w[k][nrow&63]); nrow<64 theta, >=64 phi.
__global__ void prep_b_kernel(const float* __restrict__ theta_w,
                              const float* __restrict__ phi_w)
{
    int idx = blockIdx.x * blockDim.x + threadIdx.x;   // 0..8191
    if (idx < 8192) {
        int k = idx >> 7;          // 0..63
        int c = idx & 127;         // 0..127 (coalesced read dim)
        const float* w = (c < 64) ? theta_w : phi_w;
        float v = w[k * F_DIM + (c & 63)];
        g_Bh[c * 64 + k] = __float2half_rn(v);
    }
}

// ============================ GEMM kernel ==================================
// CTA: 64 rows x full N=128 ([theta|phi]). 8 warps: wm=(wid&1)*32,
// wn=(wid>>1)*16. Warp owns theta cols wn..wn+15 and phi cols 64+wn..64+wn+15
// -> t and base combine in registers.
__global__ __launch_bounds__(256, 4)
void gemm_mma_kernel(const float* __restrict__ feat,
                     const float* __restrict__ theta_b,
                     const float* __restrict__ phi_b,
                     int n)
{
    extern __shared__ char sm[];
    const uint32_t sbase = smem_u32(sm);
    const int tid = threadIdx.x;
    const int rb  = blockIdx.x * 64;

    // ---- stage A: feat[rb..rb+63][0..63] -> fp16 hi/lo (coalesced f4) -----
#pragma unroll
    for (int p = 0; p < 4; p++) {
        int idx = tid + p * 256;         // 0..1023
        int c4  = idx & 15;              // float4 column group
        int row = idx >> 4;              // 0..63
        float4 f = make_float4(0.f, 0.f, 0.f, 0.f);
        int gr = rb + row;
        if (gr < n) f = *(const float4*)&feat[(size_t)gr * F_DIM + c4 * 4];
        uint32_t l0, l1;
        uint32_t h0 = pack_hilo(f.x, f.y, l0);
        uint32_t h1 = pack_hilo(f.z, f.w, l1);
        uint32_t off = row * 144 + c4 * 8;
        *(uint2*)(sm + SM_AH + off) = make_uint2(h0, h1);
        *(uint2*)(sm + SM_AL + off) = make_uint2(l0, l1);
    }

    // ---- stage B: copy pre-converted fp16 tile (coalesced uint4) ----------
    {
        const __half* gB = g_Bh;
#pragma unroll
        for (int p = 0; p < 4; p++) {
            int idx  = tid + p * 256;    // 0..1023
            int nrow = idx >> 3;         // 0..127
            int c8   = idx & 7;          // 16-byte chunk
            uint4 v = *(const uint4*)&gB[nrow * 64 + c8 * 8];
            *(uint4*)(sm + SM_BH + nrow * 144 + c8 * 16) = v;
        }
    }
    __syncthreads();

    const int wid  = tid >> 5;
    const int lane = tid & 31;
    const int wm   = (wid & 1) * 32;
    const int wn   = (wid >> 1) * 16;
    const int li   = lane & 7;
    const int lg   = lane >> 3;

    float accT[2][2][4], accP[2][2][4];
#pragma unroll
    for (int mt = 0; mt < 2; mt++)
#pragma unroll
        for (int nt = 0; nt < 2; nt++)
#pragma unroll
            for (int j = 0; j < 4; j++) {
                accT[mt][nt][j] = 0.f;
                accP[mt][nt][j] = 0.f;
            }

#pragma unroll
    for (int ks = 0; ks < 4; ks++) {
        const int k0 = ks * 16;
        // ---- B fragments via ldmatrix (loaded once, shared by both passes)
        uint32_t bT[2][2], bP[2][2];
        {
            int row = wn + li + (lg >> 1) * 8;
            int col = k0 + (lg & 1) * 8;
            uint32_t r[4];
            ldsm_x4(r, sbase + SM_BH + row * 144 + col * 2);
            bT[0][0] = r[0]; bT[0][1] = r[1];
            bT[1][0] = r[2]; bT[1][1] = r[3];
            ldsm_x4(r, sbase + SM_BH + (64 + row) * 144 + col * 2);
            bP[0][0] = r[0]; bP[0][1] = r[1];
            bP[1][0] = r[2]; bP[1][1] = r[3];
        }
        // ---- two A passes (hi, lo) share the B fragments -------------------
#pragma unroll
        for (int p = 0; p < 2; p++) {
            const uint32_t aoff = p ? SM_AL : SM_AH;
            uint32_t a[2][4];
#pragma unroll
            for (int mt = 0; mt < 2; mt++) {
                int row = wm + mt * 16 + li + (lg & 1) * 8;
                int col = k0 + (lg >> 1) * 8;
                ldsm_x4(a[mt], sbase + aoff + row * 144 + col * 2);
            }
#pragma unroll
            for (int mt = 0; mt < 2; mt++)
#pragma unroll
                for (int nt = 0; nt < 2; nt++) {
                    mma16816(accT[mt][nt], a[mt], bT[nt]);
                    mma16816(accP[mt][nt], a[mt], bP[nt]);
                }
        }
    }

    // ---- epilogue: t (fp16) and base (fp16) --------------------------------
#pragma unroll
    for (int mt = 0; mt < 2; mt++) {
        int r0 = rb + wm + mt * 16 + (lane >> 2);
#pragma unroll
        for (int nt = 0; nt < 2; nt++) {
            int col = wn + nt * 8 + 2 * (lane & 3);
            float b0 = theta_b[col]     + phi_b[col];
            float b1 = theta_b[col + 1] + phi_b[col + 1];
            if (r0 < n) {
                size_t o = (size_t)r0 * F_DIM + col;
                float t0 = accT[mt][nt][0], t1 = accT[mt][nt][1];
                *(__half2*)&g_t16[o] = __floats2half2_rn(t0, t1);
                *(__half2*)&g_base16[o] =
                    __floats2half2_rn(t0 + accP[mt][nt][0] + b0,
                                      t1 + accP[mt][nt][1] + b1);
            }
            int r1 = r0 + 8;
            if (r1 < n) {
                size_t o = (size_t)r1 * F_DIM + col;
                float t2 = accT[mt][nt][2], t3 = accT[mt][nt][3];
                *(__half2*)&g_t16[o] = __floats2half2_rn(t2, t3);
                *(__half2*)&g_base16[o] =
                    __floats2half2_rn(t2 + accP[mt][nt][2] + b0,
                                      t3 + accP[mt][nt][3] + b1);
            }
        }
    }
}

// ---------------------------------------------------------------------------
// Kernel 2: gather-min over fp16 t. TWO nodes per warp: lanes 0-15 -> node
// 2w, lanes 16-31 -> node 2w+1. Lane hl (0..15) owns uint2 chunk hl of the
// 128-B row (features 4hl..4hl+3). Indices: one coalesced load per lane,
// broadcast via shfl(width=16). Writes fp32 out = base16 - min (sole writer
// of out -> full coverage of the poisoned buffer).
// ---------------------------------------------------------------------------
__global__ __launch_bounds__(256)
void gather_min_kernel(const void* __restrict__ nbr_raw,
                       float* __restrict__ out,
                       int n, int K)
{
    const int lane = threadIdx.x & 31;

    // dtype detect (uniform): int64 indices < 2^31 have zero odd words
    unsigned int probe = ((const unsigned int*)nbr_raw)[lane];
    bool oddzero = ((lane & 1) == 0) || (probe == 0u);
    const bool is64 = (__ballot_sync(0xFFFFFFFFu, oddzero) == 0xFFFFFFFFu);

    long long wpair = (blockIdx.x * (long long)blockDim.x + threadIdx.x) >> 5;
    const int half = lane >> 4;      // 0 or 1
    const int hl   = lane & 15;      // chunk within row
    int node = (int)(wpair * 2) + half;
    if ((int)(wpair * 2) >= n) return;
    if (node >= n) node = n - 1;     // duplicate work on odd tail (benign)

    // my neighbor index (lane hl holds neighbor hl of my node)
    int myidx;
    if (K == 16) {
        myidx = is64 ? (int)((const long long*)nbr_raw)[(size_t)node * 16 + hl]
                     : ((const int*)nbr_raw)[(size_t)node * 16 + hl];
    } else {
        myidx = 0;
    }

    const uint2* tp = (const uint2*)g_t16;   // 16 uint2 per row
    __half2 m0 = __float2half2_rn(65504.f);
    __half2 m1 = m0;

    if (K == 16) {
#pragma unroll
        for (int j = 0; j < 16; j++) {
            int uj = __shfl_sync(0xFFFFFFFFu, myidx, j, 16);
            uint2 v = __ldg(&tp[uj * 16 + hl]);
            m0 = __hmin2(m0, *(__half2*)&v.x);
            m1 = __hmin2(m1, *(__half2*)&v.y);
        }
    } else {
        for (int j = 0; j < K; j++) {
            int uj = is64 ? (int)((const long long*)nbr_raw)[(size_t)node * K + j]
                          : ((const int*)nbr_raw)[(size_t)node * K + j];
            uint2 v = __ldg(&tp[uj * 16 + hl]);
            m0 = __hmin2(m0, *(__half2*)&v.x);
            m1 = __hmin2(m1, *(__half2*)&v.y);
        }
    }

    // base (fp16) -> out (fp32)
    size_t o = (size_t)node * 16 + hl;
    uint2 bb = *((const uint2*)g_base16 + o);
    float2 B0 = __half22float2(*(__half2*)&bb.x);
    float2 B1 = __half22float2(*(__half2*)&bb.y);
    float2 f0 = __half22float2(m0);
    float2 f1 = __half22float2(m1);
    float4* out4 = (float4*)out;
    out4[o] = make_float4(B0.x - f0.x, B0.y - f0.y,
                          B1.x - f1.x, B1.y - f1.y);
}

// ============================== launch =====================================
extern "C" void kernel_launch(void* const* d_in, const int* in_sizes, int n_in,
                              void* d_out, int out_size)
{
    const float* feat    = (const float*)d_in[0];
    const void*  nbr     = d_in[1];
    const float* theta_w = (const float*)d_in[2];
    const float* theta_b = (const float*)d_in[3];
    const float* phi_w   = (const float*)d_in[4];
    const float* phi_b   = (const float*)d_in[5];
    float* out = (float*)d_out;

    const int n = in_sizes[0] / F_DIM;     // number of nodes
    const int K = in_sizes[1] / n;         // neighbors per node (=16)

    static int smem_set = 0;
    if (!smem_set) {
        cudaFuncSetAttribute(gemm_mma_kernel,
                             cudaFuncAttributeMaxDynamicSharedMemorySize,
                             SM_BYTES);
        smem_set = 1;
    }

    prep_b_kernel<<<32, 256>>>(theta_w, phi_w);

    int g1 = (n + 63) / 64;
    gemm_mma_kernel<<<g1, 256, SM_BYTES>>>(feat, theta_b, phi_b, n);

    long long pairs = ((long long)n + 1) / 2;        // 2 nodes per warp
    long long total_threads = pairs * 32;
    int g2 = (int)((total_threads + 255) / 256);
    gather_min_kernel<<<g2, 256>>>(nbr, out, n, K);
}